// round 9
// baseline (speedup 1.0000x reference)
#include <cuda_runtime.h>

#define BB 128
#define NN 512
#define DD 300
#define AA 32

typedef unsigned long long ull;
typedef unsigned int u32;

// ---------------- helpers ----------------
__device__ __forceinline__ void fma2(ull& d, ull a, ull b) {
    asm("fma.rn.f32x2 %0, %1, %2, %0;" : "+l"(d) : "l"(a), "l"(b));
}
__device__ __forceinline__ ull dup2(float x) {
    ull r; asm("mov.b64 %0, {%1, %1};" : "=l"(r) : "f"(x)); return r;
}
__device__ __forceinline__ void unpack2(ull v, float& lo, float& hi) {
    asm("mov.b64 {%0, %1}, %2;" : "=f"(lo), "=f"(hi) : "l"(v));
}
__device__ __forceinline__ u32 tf32r(float x) {
    u32 r; asm("cvt.rna.tf32.f32 %0, %1;" : "=r"(r) : "f"(x)); return r;
}
__device__ __forceinline__ void mma8(float4& d, const u32* a, u32 b0, u32 b1) {
    asm volatile(
        "mma.sync.aligned.m16n8k8.row.col.f32.tf32.tf32.f32 "
        "{%0,%1,%2,%3}, {%4,%5,%6,%7}, {%8,%9}, {%0,%1,%2,%3};"
        : "+f"(d.x), "+f"(d.y), "+f"(d.z), "+f"(d.w)
        : "r"(a[0]), "r"(a[1]), "r"(a[2]), "r"(a[3]), "r"(b0), "r"(b1));
}
__device__ __forceinline__ u32 smem_u32(const void* p) {
    u32 a; asm("{ .reg .u64 t; cvta.to.shared.u64 t, %1; cvt.u32.u64 %0, t; }"
               : "=r"(a) : "l"(p));
    return a;
}
__device__ __forceinline__ void cp16(u32 dst, const void* src) {
    asm volatile("cp.async.cg.shared.global [%0], [%1], 16;"
                 :: "r"(dst), "l"(src) : "memory");
}
#define CP_COMMIT() asm volatile("cp.async.commit_group;" ::: "memory")
#define CP_WAIT1()  asm volatile("cp.async.wait_group 1;" ::: "memory")
#define CP_WAIT0()  asm volatile("cp.async.wait_group 0;" ::: "memory")

// Scratch: Q,K row-major [B*N, A] (tf32-rounded); Xt = X^T per batch [B][304][512]
__device__ float g_Q[BB * NN * AA];
__device__ float g_K[BB * NN * AA];
__device__ float g_Xt[(long)BB * 304 * 512];   // d rows 300..303 stay zero

// ---------------------------------------------------------------------------
// Kernel 1: Q|K projection (FFMA2) + X transpose writeout, tf32-rounded outs.
// (unchanged from round 8)
// ---------------------------------------------------------------------------
__global__ __launch_bounds__(256) void qk_kernel(
    const float* __restrict__ X,
    const float* __restrict__ Wq,
    const float* __restrict__ Wk)
{
    __shared__ float Xs[256 * 9];
    __shared__ float Ws[8 * 68];

    const int tid = threadIdx.x;
    const int row0 = blockIdx.x * 256;
    const int rg = tid >> 3;
    const int cg = tid & 7;

    ull acc[8][4];
#pragma unroll
    for (int i = 0; i < 8; i++)
#pragma unroll
        for (int j = 0; j < 4; j++) acc[i][j] = 0ull;

    float xf[8], wf[2];
    const float* xrow = X + (long)(row0 + tid) * DD;
    const int wk0 = tid >> 6, wa0 = tid & 63;
    const int wk1 = (tid + 256) >> 6, wa1 = (tid + 256) & 63;

    auto prefetch = [&](int k0) {
        if (k0 + 8 <= DD) {
            float4 v0 = *(const float4*)(xrow + k0);
            float4 v1 = *(const float4*)(xrow + k0 + 4);
            xf[0] = v0.x; xf[1] = v0.y; xf[2] = v0.z; xf[3] = v0.w;
            xf[4] = v1.x; xf[5] = v1.y; xf[6] = v1.z; xf[7] = v1.w;
        } else {
#pragma unroll
            for (int kk = 0; kk < 8; kk++)
                xf[kk] = (k0 + kk < DD) ? xrow[k0 + kk] : 0.0f;
        }
        wf[0] = (k0 + wk0 < DD)
              ? ((wa0 < 32) ? Wq[(k0 + wk0) * AA + wa0] : Wk[(k0 + wk0) * AA + wa0 - 32]) : 0.0f;
        wf[1] = (k0 + wk1 < DD)
              ? ((wa1 < 32) ? Wq[(k0 + wk1) * AA + wa1] : Wk[(k0 + wk1) * AA + wa1 - 32]) : 0.0f;
    };

    prefetch(0);

    for (int k0 = 0; k0 < DD; k0 += 8) {
        {
            float* xs = &Xs[tid * 9];
#pragma unroll
            for (int kk = 0; kk < 8; kk++) xs[kk] = xf[kk];
            Ws[wk0 * 68 + wa0] = wf[0];
            Ws[wk1 * 68 + wa1] = wf[1];
        }
        __syncthreads();
        if (k0 + 8 < DD) prefetch(k0 + 8);

        // transpose writeout: Xs[256 rows][8 d] -> g_Xt[b][d][m], tf32-rounded
        {
            const int dloc = tid >> 5, lane = tid & 31;
            const int d = k0 + dloc;
            if (d < DD) {
                const int bb = row0 >> 9;
                const int m0g = row0 & 511;
                float* dst = g_Xt + ((long)bb * 304 + d) * 512 + m0g + lane;
#pragma unroll
                for (int i = 0; i < 8; i++)
                    dst[32 * i] = __uint_as_float(tf32r(Xs[(lane + 32 * i) * 9 + dloc]));
            }
        }

#pragma unroll
        for (int k = 0; k < 8; k++) {
            ull ad[8];
#pragma unroll
            for (int i = 0; i < 8; i++) ad[i] = dup2(Xs[(rg * 8 + i) * 9 + k]);
            ull bv[4];
#pragma unroll
            for (int j = 0; j < 4; j++)
                bv[j] = *(const ull*)&Ws[k * 68 + cg * 8 + 2 * j];
#pragma unroll
            for (int i = 0; i < 8; i++)
#pragma unroll
                for (int j = 0; j < 4; j++) fma2(acc[i][j], bv[j], ad[i]);
        }
        __syncthreads();
    }

#pragma unroll
    for (int i = 0; i < 8; i++) {
        const int row = row0 + rg * 8 + i;
#pragma unroll
        for (int j = 0; j < 4; j++) {
            const int c = cg * 8 + 2 * j;
            float lo, hi; unpack2(acc[i][j], lo, hi);
            ull packed = (ull)tf32r(lo) | ((ull)tf32r(hi) << 32);
            if (c < 32) *(ull*)&g_Q[row * AA + c] = packed;
            else        *(ull*)&g_K[row * AA + (c - 32)] = packed;
        }
    }
}

// ---------------------------------------------------------------------------
// Kernel 2: warp-MMA (tf32) fused attention, cp.async double-buffered.
// Block = 1 batch x 64 q rows, 256 thr.
// 8 warps = 2 q-groups (32 rows = 2 x m16) x 4 d-slices (80/80/80/64).
// X B-fragments loaded once per warp, shared by both row-tiles.
// smem per buffer: Xs [304 d][stride 160B] = 48640 ; Ks [32 m][128B swz] = 4096
// ---------------------------------------------------------------------------
#define XSTRIDE 160
#define KOFF    48640
#define BUFSZ   52736
#define SM_TOT  (2 * BUFSZ)

__global__ __launch_bounds__(256, 1) void attn_mma_kernel(
    const float* __restrict__ adj,
    float* __restrict__ out)
{
    extern __shared__ char smc[];
    const u32 sb = smem_u32(smc);
    const int tid = threadIdx.x;
    const int lane = tid & 31, w = tid >> 5;
    const int g = lane >> 2, t = lane & 3;
    const int qg = w & 1;            // 2 q-groups of 32 rows
    const int dh = w >> 1;           // 4 d-slices
    const int NT = (dh < 3) ? 10 : 8;
    const int d0 = dh * 80;
    const int b = blockIdx.x >> 3, row0 = (blockIdx.x & 7) * 64;
    const int qbase = b * NN + row0 + qg * 32;

    // ---- staging (cp.async) ----
    auto stage = [&](int cc, int bi) {
        const int m0s = cc * 32;
        const u32 bx = sb + bi * BUFSZ;
        {   // Ks: 32 rows x 2 x 16B
            int row = tid >> 3, m4 = tid & 7;
            u32 dst = bx + KOFF + row * 128 + ((m4 * 16) ^ ((row & 7) << 4));
            cp16(dst, g_K + ((long)(b * NN + m0s + row)) * AA + m4 * 4);
        }
#pragma unroll
        for (int tt = 0; tt < 10; tt++) {   // Xs: 304 rows x 8 x 16B = 2432 cps
            int idx = tid + tt * 256;
            if (idx < 2432) {
                int d = idx >> 3, m4 = idx & 7;
                u32 dst = bx + d * XSTRIDE + m4 * 16;
                cp16(dst, g_Xt + ((long)b * 304 + d) * 512 + m0s + m4 * 4);
            }
        }
    };

    stage(0, 0);
    CP_COMMIT();

    float4 oacc[2][10];
#pragma unroll
    for (int rt = 0; rt < 2; rt++)
#pragma unroll
        for (int nt = 0; nt < 10; nt++) oacc[rt][nt] = make_float4(0.f, 0.f, 0.f, 0.f);
    float rs[2][2] = {0.f, 0.f, 0.f, 0.f};

#pragma unroll 1
    for (int c = 0; c < 16; c++) {
        if (c < 15) {
            stage(c + 1, (c + 1) & 1);
            CP_COMMIT();
            CP_WAIT1();
        } else {
            CP_WAIT0();
        }
        __syncthreads();

        const char* xb = smc + (c & 1) * BUFSZ;
        const char* kb = xb + KOFF;
        const int m0 = c * 32;

        // ---- all K fragments for this chunk (shared across both rt) ----
        u32 kf[4][8];
#pragma unroll
        for (int mnt = 0; mnt < 4; mnt++) {
            const char* krow = kb + (8 * mnt + g) * 128;
#pragma unroll
            for (int kt = 0; kt < 4; kt++) {
                kf[mnt][2 * kt]     = *(const u32*)(krow + (((8 * kt + t) * 4) ^ (g << 4)));
                kf[mnt][2 * kt + 1] = *(const u32*)(krow + (((8 * kt + t + 4) * 4) ^ (g << 4)));
            }
        }

        // ---- S = Q K^T per rt, fused exp(s*adj) -> P A-fragments ----
        u32 pa[2][4][4];
#pragma unroll
        for (int rt = 0; rt < 2; rt++) {
            // Q fragments (g_Q is L1-hot; reload per chunk to cap registers)
            const float* q0 = g_Q + (long)(qbase + rt * 16 + g) * AA;
            const float* q1 = g_Q + (long)(qbase + rt * 16 + 8 + g) * AA;
            u32 qa[4][4];
#pragma unroll
            for (int kt = 0; kt < 4; kt++) {
                qa[kt][0] = __float_as_uint(q0[8 * kt + t]);
                qa[kt][1] = __float_as_uint(q1[8 * kt + t]);
                qa[kt][2] = __float_as_uint(q0[8 * kt + t + 4]);
                qa[kt][3] = __float_as_uint(q1[8 * kt + t + 4]);
            }
            // adj fragments
            const float* a0p = adj + (long)(qbase + rt * 16 + g) * NN + 2 * t + m0;
            const float* a1p = adj + (long)(qbase + rt * 16 + 8 + g) * NN + 2 * t + m0;
            ull aj0[4], aj1[4];
#pragma unroll
            for (int mnt = 0; mnt < 4; mnt++) {
                aj0[mnt] = *(const ull*)(a0p + mnt * 8);
                aj1[mnt] = *(const ull*)(a1p + mnt * 8);
            }
#pragma unroll
            for (int mnt = 0; mnt < 4; mnt++) {
                float4 s = make_float4(0.f, 0.f, 0.f, 0.f);
#pragma unroll
                for (int kt = 0; kt < 4; kt++)
                    mma8(s, qa[kt], kf[mnt][2 * kt], kf[mnt][2 * kt + 1]);
                float ax, ay, az, aw;
                unpack2(aj0[mnt], ax, ay);
                unpack2(aj1[mnt], az, aw);
                u32 p0 = tf32r(__expf(s.x * ax));
                u32 p1 = tf32r(__expf(s.y * ay));
                u32 p2 = tf32r(__expf(s.z * az));
                u32 p3 = tf32r(__expf(s.w * aw));
                rs[rt][0] += __uint_as_float(p0) + __uint_as_float(p1);
                rs[rt][1] += __uint_as_float(p2) + __uint_as_float(p3);
                // C-frag (c0,c1,c2,c3) -> A-frag = (c0, c2, c1, c3)
                pa[rt][mnt][0] = p0; pa[rt][mnt][1] = p2;
                pa[rt][mnt][2] = p1; pa[rt][mnt][3] = p3;
            }
        }

        // ---- O += P @ X^T : one B-frag load feeds BOTH row-tiles ----
#pragma unroll
        for (int nt = 0; nt < 10; nt++) {
            if (nt < NT) {
                const char* xrow = xb + (d0 + nt * 8 + g) * XSTRIDE;
#pragma unroll
                for (int kt = 0; kt < 4; kt++) {
                    ull xv = *(const ull*)(xrow + kt * 32 + 8 * t);
                    mma8(oacc[0][nt], pa[0][kt], (u32)xv, (u32)(xv >> 32));
                    mma8(oacc[1][nt], pa[1][kt], (u32)xv, (u32)(xv >> 32));
                }
            }
        }
        __syncthreads();   // all reads of buf (c&1) done before it is restaged
    }

    // ---- rowsum reduce across the t-quad ----
#pragma unroll
    for (int rt = 0; rt < 2; rt++)
#pragma unroll
        for (int h = 0; h < 2; h++) {
            float v = rs[rt][h];
            v += __shfl_xor_sync(0xffffffffu, v, 1);
            v += __shfl_xor_sync(0xffffffffu, v, 2);
            rs[rt][h] = v;
        }

    // ---- normalize + store ----
#pragma unroll
    for (int rt = 0; rt < 2; rt++) {
        const float i0 = 1.0f / rs[rt][0];
        const float i1 = 1.0f / rs[rt][1];
        float* r0p = out + (long)(qbase + rt * 16 + g) * DD;
        float* r1p = out + (long)(qbase + rt * 16 + 8 + g) * DD;
#pragma unroll
        for (int nt = 0; nt < 10; nt++) {
            if (nt < NT) {
                const int d = d0 + nt * 8 + 2 * t;
                if (d < 299) {
                    *(float2*)(r0p + d) = make_float2(oacc[rt][nt].x * i0, oacc[rt][nt].y * i0);
                    *(float2*)(r1p + d) = make_float2(oacc[rt][nt].z * i1, oacc[rt][nt].w * i1);
                }
            }
        }
    }
}

// ---------------------------------------------------------------------------
extern "C" void kernel_launch(void* const* d_in, const int* in_sizes, int n_in,
                              void* d_out, int out_size)
{
    const float* X   = (const float*)d_in[0];
    const float* adj = (const float*)d_in[1];
    const float* Wq  = (const float*)d_in[2];
    const float* Wk  = (const float*)d_in[3];
    float* out = (float*)d_out;

    cudaFuncSetAttribute(attn_mma_kernel,
                         cudaFuncAttributeMaxDynamicSharedMemorySize, SM_TOT);

    qk_kernel<<<(BB * NN) / 256, 256>>>(X, Wq, Wk);
    attn_mma_kernel<<<BB * 8, 256, SM_TOT>>>(adj, out);
}

// round 12
// speedup vs baseline: 1.6716x; 1.6716x over previous
#include <cuda_runtime.h>

#define BB 128
#define NN 512
#define DD 300
#define AA 32

typedef unsigned long long ull;
typedef unsigned int u32;

// ---------------- helpers ----------------
__device__ __forceinline__ void fma2(ull& d, ull a, ull b) {
    asm("fma.rn.f32x2 %0, %1, %2, %0;" : "+l"(d) : "l"(a), "l"(b));
}
__device__ __forceinline__ ull dup2(float x) {
    ull r; asm("mov.b64 %0, {%1, %1};" : "=l"(r) : "f"(x)); return r;
}
__device__ __forceinline__ void unpack2(ull v, float& lo, float& hi) {
    asm("mov.b64 {%0, %1}, %2;" : "=f"(lo), "=f"(hi) : "l"(v));
}
__device__ __forceinline__ u32 tf32r(float x) {
    u32 r; asm("cvt.rna.tf32.f32 %0, %1;" : "=r"(r) : "f"(x)); return r;
}
__device__ __forceinline__ void mma8(float4& d, const u32* a, u32 b0, u32 b1) {
    asm volatile(
        "mma.sync.aligned.m16n8k8.row.col.f32.tf32.tf32.f32 "
        "{%0,%1,%2,%3}, {%4,%5,%6,%7}, {%8,%9}, {%0,%1,%2,%3};"
        : "+f"(d.x), "+f"(d.y), "+f"(d.z), "+f"(d.w)
        : "r"(a[0]), "r"(a[1]), "r"(a[2]), "r"(a[3]), "r"(b0), "r"(b1));
}
__device__ __forceinline__ u32 smem_u32(const void* p) {
    u32 a; asm("{ .reg .u64 t; cvta.to.shared.u64 t, %1; cvt.u32.u64 %0, t; }"
               : "=r"(a) : "l"(p));
    return a;
}
__device__ __forceinline__ void cp16(u32 dst, const void* src) {
    asm volatile("cp.async.cg.shared.global [%0], [%1], 16;"
                 :: "r"(dst), "l"(src) : "memory");
}
#define CP_COMMIT() asm volatile("cp.async.commit_group;" ::: "memory")
#define CP_WAIT1()  asm volatile("cp.async.wait_group 1;" ::: "memory")
#define CP_WAIT0()  asm volatile("cp.async.wait_group 0;" ::: "memory")

// Scratch: Q,K row-major [B*N, A] (tf32-rounded); Xt = X^T per batch [B][304][512]
__device__ float g_Q[BB * NN * AA];
__device__ float g_K[BB * NN * AA];
__device__ float g_Xt[(long)BB * 304 * 512];   // d rows 300..303 stay zero

// ---------------------------------------------------------------------------
// Kernel 1: Q|K projection (FFMA2) + X transpose writeout, tf32-rounded outs.
// Retiled: 128 rows x 64 cols per block (grid 512), micro-tile 4x8.
// ---------------------------------------------------------------------------
__global__ __launch_bounds__(256) void qk_kernel(
    const float* __restrict__ X,
    const float* __restrict__ Wq,
    const float* __restrict__ Wk)
{
    __shared__ float Xs[128 * 9];
    __shared__ float Ws[8 * 68];

    const int tid = threadIdx.x;
    const int row0 = blockIdx.x * 128;
    const int rg = tid >> 3;        // 0..31 -> rows rg*4..rg*4+3
    const int cg = tid & 7;         // cols cg*8..+7

    ull acc[4][4];
#pragma unroll
    for (int i = 0; i < 4; i++)
#pragma unroll
        for (int j = 0; j < 4; j++) acc[i][j] = 0ull;

    // X staging: thread -> (row = tid>>1, half = tid&1), 4 floats
    const int xr = tid >> 1, xh = tid & 1;
    const float* xrow = X + (long)(row0 + xr) * DD + xh * 4;
    float xf[4], wf[2];
    const int wk0 = tid >> 6, wa0 = tid & 63;
    const int wk1 = (tid + 256) >> 6, wa1 = (tid + 256) & 63;

    auto prefetch = [&](int k0) {
        if (k0 + xh * 4 + 4 <= DD) {
            float4 v = *(const float4*)(xrow + k0);
            xf[0] = v.x; xf[1] = v.y; xf[2] = v.z; xf[3] = v.w;
        } else {
#pragma unroll
            for (int kk = 0; kk < 4; kk++)
                xf[kk] = (k0 + xh * 4 + kk < DD) ? xrow[k0 + kk] : 0.0f;
        }
        wf[0] = (k0 + wk0 < DD)
              ? ((wa0 < 32) ? Wq[(k0 + wk0) * AA + wa0] : Wk[(k0 + wk0) * AA + wa0 - 32]) : 0.0f;
        wf[1] = (k0 + wk1 < DD)
              ? ((wa1 < 32) ? Wq[(k0 + wk1) * AA + wa1] : Wk[(k0 + wk1) * AA + wa1 - 32]) : 0.0f;
    };

    prefetch(0);

    for (int k0 = 0; k0 < DD; k0 += 8) {
        {
            float* xs = &Xs[xr * 9 + xh * 4];
#pragma unroll
            for (int kk = 0; kk < 4; kk++) xs[kk] = xf[kk];
            Ws[wk0 * 68 + wa0] = wf[0];
            Ws[wk1 * 68 + wa1] = wf[1];
        }
        __syncthreads();
        if (k0 + 8 < DD) prefetch(k0 + 8);

        // transpose writeout: Xs[128 rows][8 d] -> g_Xt[b][d][m], tf32-rounded
        {
            const int dloc = tid >> 5, lane = tid & 31;
            const int d = k0 + dloc;
            if (d < DD) {
                const int bb = row0 >> 9;
                const int m0g = row0 & 511;
                float* dst = g_Xt + ((long)bb * 304 + d) * 512 + m0g + lane;
#pragma unroll
                for (int i = 0; i < 4; i++)
                    dst[32 * i] = __uint_as_float(tf32r(Xs[(lane + 32 * i) * 9 + dloc]));
            }
        }

#pragma unroll
        for (int k = 0; k < 8; k++) {
            ull ad[4];
#pragma unroll
            for (int i = 0; i < 4; i++) ad[i] = dup2(Xs[(rg * 4 + i) * 9 + k]);
            ull bv[4];
#pragma unroll
            for (int j = 0; j < 4; j++)
                bv[j] = *(const ull*)&Ws[k * 68 + cg * 8 + 2 * j];
#pragma unroll
            for (int i = 0; i < 4; i++)
#pragma unroll
                for (int j = 0; j < 4; j++) fma2(acc[i][j], bv[j], ad[i]);
        }
        __syncthreads();
    }

#pragma unroll
    for (int i = 0; i < 4; i++) {
        const int row = row0 + rg * 4 + i;
#pragma unroll
        for (int j = 0; j < 4; j++) {
            const int c = cg * 8 + 2 * j;
            float lo, hi; unpack2(acc[i][j], lo, hi);
            ull packed = (ull)tf32r(lo) | ((ull)tf32r(hi) << 32);
            if (c < 32) *(ull*)&g_Q[row * AA + c] = packed;
            else        *(ull*)&g_K[row * AA + (c - 32)] = packed;
        }
    }
}

// ---------------------------------------------------------------------------
// Kernel 2: warp-MMA (tf32) fused attention, cp.async double-buffered.
// (exact round-8 version: 4 q-groups(16 rows) x 2 d-halves, regs ~217)
// smem per buffer: Xs [304 d][stride 160B] = 48640 ; Ks [32 m][128B swz] = 4096
// ---------------------------------------------------------------------------
#define XSTRIDE 160
#define KOFF    48640
#define BUFSZ   52736
#define SM_TOT  (2 * BUFSZ)

__global__ __launch_bounds__(256, 1) void attn_mma_kernel(
    const float* __restrict__ adj,
    float* __restrict__ out)
{
    extern __shared__ char smc[];
    const u32 sb = smem_u32(smc);
    const int tid = threadIdx.x;
    const int lane = tid & 31, w = tid >> 5;
    const int g = lane >> 2, t = lane & 3;
    const int qg = w & 3, dh = w >> 2;
    const int b = blockIdx.x >> 3, row0 = (blockIdx.x & 7) * 64;
    const int qbase = b * NN + row0 + qg * 16;   // 16 q rows per group

    // ---- staging lambda (cp.async, one commit per call) ----
    auto stage = [&](int cc, int bi) {
        const int m0 = cc * 32;
        const u32 bx = sb + bi * BUFSZ;
        {   // Ks: 32 rows x 2 x 16B ; 256 cps
            int row = tid >> 3, m4 = tid & 7;
            u32 dst = bx + KOFF + row * 128 + ((m4 * 16) ^ ((row & 7) << 4));
            cp16(dst, g_K + ((long)(b * NN + m0 + row)) * AA + m4 * 4);
        }
#pragma unroll
        for (int tt = 0; tt < 10; tt++) {   // Xs: 304 rows x 8 x 16B = 2432 cps
            int idx = tid + tt * 256;
            if (idx < 2432) {
                int d = idx >> 3, m4 = idx & 7;
                u32 dst = bx + d * XSTRIDE + m4 * 16;
                cp16(dst, g_Xt + ((long)b * 304 + d) * 512 + m0 + m4 * 4);
            }
        }
    };

    // ---- adj fragment prefetch (direct LDG.64, natural layout) ----
    ull ajc0[4], ajc1[4], ajn0[4], ajn1[4];
    const float* ar0 = adj + (long)(qbase + g) * NN + 2 * t;
    const float* ar1 = adj + (long)(qbase + 8 + g) * NN + 2 * t;
    auto adjload = [&](int cc, ull* a0, ull* a1) {
        const int m0 = cc * 32;
#pragma unroll
        for (int mnt = 0; mnt < 4; mnt++) {
            a0[mnt] = *(const ull*)(ar0 + m0 + mnt * 8);
            a1[mnt] = *(const ull*)(ar1 + m0 + mnt * 8);
        }
    };

    // ---- Q fragments: persistent in registers ----
    u32 qa[4][4];
    {
        const float* q0 = g_Q + (long)(qbase + g) * AA;
        const float* q1 = g_Q + (long)(qbase + 8 + g) * AA;
#pragma unroll
        for (int kt = 0; kt < 4; kt++) {
            qa[kt][0] = __float_as_uint(q0[8 * kt + t]);
            qa[kt][1] = __float_as_uint(q1[8 * kt + t]);
            qa[kt][2] = __float_as_uint(q0[8 * kt + t + 4]);
            qa[kt][3] = __float_as_uint(q1[8 * kt + t + 4]);
        }
    }

    stage(0, 0);
    CP_COMMIT();
    adjload(0, ajc0, ajc1);

    float4 oacc[19];
#pragma unroll
    for (int nt = 0; nt < 19; nt++) oacc[nt] = make_float4(0.f, 0.f, 0.f, 0.f);
    float r0s = 0.f, r1s = 0.f;

#pragma unroll 1
    for (int c = 0; c < 16; c++) {
        if (c < 15) {
            stage(c + 1, (c + 1) & 1);
            CP_COMMIT();
            CP_WAIT1();
        } else {
            CP_WAIT0();
        }
        __syncthreads();

        const char* xb = smc + (c & 1) * BUFSZ;
        const char* kb = xb + KOFF;

        // ---- S = Q K^T per mnt, fused exp(s*adj), build A-frags of P ----
        u32 pa[4][4];
#pragma unroll
        for (int mnt = 0; mnt < 4; mnt++) {
            const char* krow = kb + (8 * mnt + g) * 128;
            float4 s = make_float4(0.f, 0.f, 0.f, 0.f);
#pragma unroll
            for (int kt = 0; kt < 4; kt++) {
                u32 b0 = *(const u32*)(krow + (((8 * kt + t) * 4) ^ (g << 4)));
                u32 b1 = *(const u32*)(krow + (((8 * kt + t + 4) * 4) ^ (g << 4)));
                mma8(s, qa[kt], b0, b1);
            }
            float ax, ay, az, aw;
            unpack2(ajc0[mnt], ax, ay);
            unpack2(ajc1[mnt], az, aw);
            u32 p0 = tf32r(__expf(s.x * ax));
            u32 p1 = tf32r(__expf(s.y * ay));
            u32 p2 = tf32r(__expf(s.z * az));
            u32 p3 = tf32r(__expf(s.w * aw));
            r0s += __uint_as_float(p0) + __uint_as_float(p1);
            r1s += __uint_as_float(p2) + __uint_as_float(p3);
            // C-frag (c0,c1,c2,c3) -> A-frag = (c0, c2, c1, c3)
            pa[mnt][0] = p0; pa[mnt][1] = p2; pa[mnt][2] = p1; pa[mnt][3] = p3;
        }

        // prefetch next adj chunk under the AV MMAs
        if (c < 15) adjload(c + 1, ajn0, ajn1);

        // ---- O += P @ X^T ----
#pragma unroll
        for (int nt = 0; nt < 19; nt++) {
            const char* xrow = xb + (dh * 152 + nt * 8 + g) * XSTRIDE;
#pragma unroll
            for (int kt = 0; kt < 4; kt++) {
                ull xv = *(const ull*)(xrow + kt * 32 + 8 * t);
                mma8(oacc[nt], pa[kt], (u32)xv, (u32)(xv >> 32));
            }
        }

#pragma unroll
        for (int mnt = 0; mnt < 4; mnt++) { ajc0[mnt] = ajn0[mnt]; ajc1[mnt] = ajn1[mnt]; }
        __syncthreads();   // all reads of buf (c&1) done before it is restaged
    }

    // ---- rowsum reduce across the t-quad ----
    {
        float v = r0s;
        v += __shfl_xor_sync(0xffffffffu, v, 1);
        v += __shfl_xor_sync(0xffffffffu, v, 2);
        r0s = v;
        v = r1s;
        v += __shfl_xor_sync(0xffffffffu, v, 1);
        v += __shfl_xor_sync(0xffffffffu, v, 2);
        r1s = v;
    }

    // ---- normalize + store ----
    {
        const float i0 = 1.0f / r0s;
        const float i1 = 1.0f / r1s;
        float* r0p = out + (long)(qbase + g) * DD;
        float* r1p = out + (long)(qbase + 8 + g) * DD;
#pragma unroll
        for (int nt = 0; nt < 19; nt++) {
            const int d = dh * 152 + nt * 8 + 2 * t;
            if (d < 299) {
                *(float2*)(r0p + d) = make_float2(oacc[nt].x * i0, oacc[nt].y * i0);
                *(float2*)(r1p + d) = make_float2(oacc[nt].z * i1, oacc[nt].w * i1);
            }
        }
    }
}

// ---------------------------------------------------------------------------
extern "C" void kernel_launch(void* const* d_in, const int* in_sizes, int n_in,
                              void* d_out, int out_size)
{
    const float* X   = (const float*)d_in[0];
    const float* adj = (const float*)d_in[1];
    const float* Wq  = (const float*)d_in[2];
    const float* Wk  = (const float*)d_in[3];
    float* out = (float*)d_out;

    cudaFuncSetAttribute(attn_mma_kernel,
                         cudaFuncAttributeMaxDynamicSharedMemorySize, SM_TOT);

    qk_kernel<<<(BB * NN) / 128, 256>>>(X, Wq, Wk);
    attn_mma_kernel<<<BB * 8, 256, SM_TOT>>>(adj, out);
}

// round 14
// speedup vs baseline: 1.7311x; 1.0356x over previous
#include <cuda_runtime.h>

#define BB 128
#define NN 512
#define DD 300
#define AA 32

typedef unsigned long long ull;
typedef unsigned int u32;

// ---------------- helpers ----------------
__device__ __forceinline__ void fma2(ull& d, ull a, ull b) {
    asm("fma.rn.f32x2 %0, %1, %2, %0;" : "+l"(d) : "l"(a), "l"(b));
}
__device__ __forceinline__ ull dup2(float x) {
    ull r; asm("mov.b64 %0, {%1, %1};" : "=l"(r) : "f"(x)); return r;
}
__device__ __forceinline__ void unpack2(ull v, float& lo, float& hi) {
    asm("mov.b64 {%0, %1}, %2;" : "=f"(lo), "=f"(hi) : "l"(v));
}
__device__ __forceinline__ u32 tf32r(float x) {
    u32 r; asm("cvt.rna.tf32.f32 %0, %1;" : "=r"(r) : "f"(x)); return r;
}
__device__ __forceinline__ void mma8(float4& d, const u32* a, u32 b0, u32 b1) {
    asm volatile(
        "mma.sync.aligned.m16n8k8.row.col.f32.tf32.tf32.f32 "
        "{%0,%1,%2,%3}, {%4,%5,%6,%7}, {%8,%9}, {%0,%1,%2,%3};"
        : "+f"(d.x), "+f"(d.y), "+f"(d.z), "+f"(d.w)
        : "r"(a[0]), "r"(a[1]), "r"(a[2]), "r"(a[3]), "r"(b0), "r"(b1));
}
__device__ __forceinline__ u32 smem_u32(const void* p) {
    u32 a; asm("{ .reg .u64 t; cvta.to.shared.u64 t, %1; cvt.u32.u64 %0, t; }"
               : "=r"(a) : "l"(p));
    return a;
}
__device__ __forceinline__ void cp16(u32 dst, const void* src) {
    asm volatile("cp.async.cg.shared.global [%0], [%1], 16;"
                 :: "r"(dst), "l"(src) : "memory");
}
#define CP_COMMIT() asm volatile("cp.async.commit_group;" ::: "memory")
#define CP_WAIT1()  asm volatile("cp.async.wait_group 1;" ::: "memory")
#define CP_WAIT0()  asm volatile("cp.async.wait_group 0;" ::: "memory")

// Scratch: Q,K row-major [B*N, A] (tf32-rounded); Xt = X^T per batch [B][304][512]
__device__ float g_Q[BB * NN * AA];
__device__ float g_K[BB * NN * AA];
__device__ float g_Xt[(long)BB * 304 * 512];   // d rows 300..303 stay zero

// ---------------------------------------------------------------------------
// Kernel 1: Q|K projection (FFMA2) + X transpose writeout, tf32-rounded outs.
// cp.async double-buffered: 128 rows x 64 cols per block (grid 512),
// k-chunks of 20 (300 = 15 x 20, no partial chunks).
// ---------------------------------------------------------------------------
#define KCH 20

__global__ __launch_bounds__(256) void qk_kernel(
    const float* __restrict__ X,
    const float* __restrict__ Wq,
    const float* __restrict__ Wk)
{
    __shared__ float Xs[2][128 * KCH];   // rows of 20 floats
    __shared__ float Ws[2][KCH * 68];    // 20 k x 64 cols, stride 68

    const int tid = threadIdx.x;
    const int row0 = blockIdx.x * 128;
    const int rg = tid >> 3;        // 0..31 -> rows rg*4..rg*4+3
    const int cg = tid & 7;         // cols cg*8..+7
    const int lane = tid & 31;

    const u32 xs0 = smem_u32(&Xs[0][0]);
    const u32 ws0 = smem_u32(&Ws[0][0]);

    // ---- staging: one chunk = 640 X cps + 320 W cps ----
    auto stage = [&](int c, int bi) {
        const int k0 = c * KCH;
        const u32 xb = xs0 + bi * (128 * KCH * 4);
        const u32 wb = ws0 + bi * (KCH * 68 * 4);
        // X: 128 rows x 5 float4
#pragma unroll
        for (int tt = 0; tt < 3; tt++) {
            int idx = tid + tt * 256;
            if (idx < 640) {
                int r = idx / 5, j = idx % 5;
                cp16(xb + (r * KCH + j * 4) * 4,
                     X + (long)(row0 + r) * DD + k0 + j * 4);
            }
        }
        // W: 20 k x 16 float4 (Wq cols 0..31 | Wk cols 32..63) — 320 cps
#pragma unroll
        for (int tt = 0; tt < 2; tt++) {
            int idx = tid + tt * 256;
            if (idx < 320) {
                int kk = idx >> 4, sub = idx & 15;
                int a4 = sub * 4;
                const float* src = (a4 < 32)
                    ? (Wq + (k0 + kk) * AA + a4)
                    : (Wk + (k0 + kk) * AA + (a4 - 32));
                cp16(wb + (kk * 68 + a4) * 4, src);
            }
        }
    };

    ull acc[4][4];
#pragma unroll
    for (int i = 0; i < 4; i++)
#pragma unroll
        for (int j = 0; j < 4; j++) acc[i][j] = 0ull;

    stage(0, 0);
    CP_COMMIT();

#pragma unroll 1
    for (int c = 0; c < 15; c++) {
        if (c < 14) {
            stage(c + 1, (c + 1) & 1);
            CP_COMMIT();
            CP_WAIT1();
        } else {
            CP_WAIT0();
        }
        __syncthreads();

        const float* xs = &Xs[c & 1][0];
        const float* ws = &Ws[c & 1][0];
        const int k0 = c * KCH;

        // ---- transpose writeout: Xs[128 rows][20 d] -> g_Xt[b][d][m] ----
        {
            const int bb = row0 >> 9;
            const int m0g = row0 & 511;
#pragma unroll
            for (int it = 0; it < 3; it++) {
                const int dl = it * 8 + (tid >> 5);
                if (dl < KCH) {
                    const int d = k0 + dl;   // always < 300
                    float* dst = g_Xt + ((long)bb * 304 + d) * 512 + m0g + lane;
#pragma unroll
                    for (int i = 0; i < 4; i++)
                        dst[32 * i] = __uint_as_float(tf32r(xs[(lane + 32 * i) * KCH + dl]));
                }
            }
        }

        // ---- FFMA2 compute over 20 k ----
#pragma unroll
        for (int k = 0; k < KCH; k++) {
            ull ad[4];
#pragma unroll
            for (int i = 0; i < 4; i++) ad[i] = dup2(xs[(rg * 4 + i) * KCH + k]);
            ull bv[4];
#pragma unroll
            for (int j = 0; j < 4; j++)
                bv[j] = *(const ull*)&ws[k * 68 + cg * 8 + 2 * j];
#pragma unroll
            for (int i = 0; i < 4; i++)
#pragma unroll
                for (int j = 0; j < 4; j++) fma2(acc[i][j], bv[j], ad[i]);
        }
        __syncthreads();
    }

    // ---- store Q | K (tf32-rounded, packed) ----
#pragma unroll
    for (int i = 0; i < 4; i++) {
        const int row = row0 + rg * 4 + i;
#pragma unroll
        for (int j = 0; j < 4; j++) {
            const int c = cg * 8 + 2 * j;
            float lo, hi; unpack2(acc[i][j], lo, hi);
            ull packed = (ull)tf32r(lo) | ((ull)tf32r(hi) << 32);
            if (c < 32) *(ull*)&g_Q[row * AA + c] = packed;
            else        *(ull*)&g_K[row * AA + (c - 32)] = packed;
        }
    }
}

// ---------------------------------------------------------------------------
// Kernel 2: warp-MMA (tf32) fused attention, cp.async double-buffered.
// (exact round-8 version: 4 q-groups(16 rows) x 2 d-halves, regs ~217)
// smem per buffer: Xs [304 d][stride 160B] = 48640 ; Ks [32 m][128B swz] = 4096
// ---------------------------------------------------------------------------
#define XSTRIDE 160
#define KOFF    48640
#define BUFSZ   52736
#define SM_TOT  (2 * BUFSZ)

__global__ __launch_bounds__(256, 1) void attn_mma_kernel(
    const float* __restrict__ adj,
    float* __restrict__ out)
{
    extern __shared__ char smc[];
    const u32 sb = smem_u32(smc);
    const int tid = threadIdx.x;
    const int lane = tid & 31, w = tid >> 5;
    const int g = lane >> 2, t = lane & 3;
    const int qg = w & 3, dh = w >> 2;
    const int b = blockIdx.x >> 3, row0 = (blockIdx.x & 7) * 64;
    const int qbase = b * NN + row0 + qg * 16;   // 16 q rows per group

    // ---- staging lambda (cp.async, one commit per call) ----
    auto stage = [&](int cc, int bi) {
        const int m0 = cc * 32;
        const u32 bx = sb + bi * BUFSZ;
        {   // Ks: 32 rows x 2 x 16B ; 256 cps
            int row = tid >> 3, m4 = tid & 7;
            u32 dst = bx + KOFF + row * 128 + ((m4 * 16) ^ ((row & 7) << 4));
            cp16(dst, g_K + ((long)(b * NN + m0 + row)) * AA + m4 * 4);
        }
#pragma unroll
        for (int tt = 0; tt < 10; tt++) {   // Xs: 304 rows x 8 x 16B = 2432 cps
            int idx = tid + tt * 256;
            if (idx < 2432) {
                int d = idx >> 3, m4 = idx & 7;
                u32 dst = bx + d * XSTRIDE + m4 * 16;
                cp16(dst, g_Xt + ((long)b * 304 + d) * 512 + m0 + m4 * 4);
            }
        }
    };

    // ---- adj fragment prefetch (direct LDG.64, natural layout) ----
    ull ajc0[4], ajc1[4], ajn0[4], ajn1[4];
    const float* ar0 = adj + (long)(qbase + g) * NN + 2 * t;
    const float* ar1 = adj + (long)(qbase + 8 + g) * NN + 2 * t;
    auto adjload = [&](int cc, ull* a0, ull* a1) {
        const int m0 = cc * 32;
#pragma unroll
        for (int mnt = 0; mnt < 4; mnt++) {
            a0[mnt] = *(const ull*)(ar0 + m0 + mnt * 8);
            a1[mnt] = *(const ull*)(ar1 + m0 + mnt * 8);
        }
    };

    // ---- Q fragments: persistent in registers ----
    u32 qa[4][4];
    {
        const float* q0 = g_Q + (long)(qbase + g) * AA;
        const float* q1 = g_Q + (long)(qbase + 8 + g) * AA;
#pragma unroll
        for (int kt = 0; kt < 4; kt++) {
            qa[kt][0] = __float_as_uint(q0[8 * kt + t]);
            qa[kt][1] = __float_as_uint(q1[8 * kt + t]);
            qa[kt][2] = __float_as_uint(q0[8 * kt + t + 4]);
            qa[kt][3] = __float_as_uint(q1[8 * kt + t + 4]);
        }
    }

    stage(0, 0);
    CP_COMMIT();
    adjload(0, ajc0, ajc1);

    float4 oacc[19];
#pragma unroll
    for (int nt = 0; nt < 19; nt++) oacc[nt] = make_float4(0.f, 0.f, 0.f, 0.f);
    float r0s = 0.f, r1s = 0.f;

#pragma unroll 1
    for (int c = 0; c < 16; c++) {
        if (c < 15) {
            stage(c + 1, (c + 1) & 1);
            CP_COMMIT();
            CP_WAIT1();
        } else {
            CP_WAIT0();
        }
        __syncthreads();

        const char* xb = smc + (c & 1) * BUFSZ;
        const char* kb = xb + KOFF;

        // ---- S = Q K^T per mnt, fused exp(s*adj), build A-frags of P ----
        u32 pa[4][4];
#pragma unroll
        for (int mnt = 0; mnt < 4; mnt++) {
            const char* krow = kb + (8 * mnt + g) * 128;
            float4 s = make_float4(0.f, 0.f, 0.f, 0.f);
#pragma unroll
            for (int kt = 0; kt < 4; kt++) {
                u32 b0 = *(const u32*)(krow + (((8 * kt + t) * 4) ^ (g << 4)));
                u32 b1 = *(const u32*)(krow + (((8 * kt + t + 4) * 4) ^ (g << 4)));
                mma8(s, qa[kt], b0, b1);
            }
            float ax, ay, az, aw;
            unpack2(ajc0[mnt], ax, ay);
            unpack2(ajc1[mnt], az, aw);
            u32 p0 = tf32r(__expf(s.x * ax));
            u32 p1 = tf32r(__expf(s.y * ay));
            u32 p2 = tf32r(__expf(s.z * az));
            u32 p3 = tf32r(__expf(s.w * aw));
            r0s += __uint_as_float(p0) + __uint_as_float(p1);
            r1s += __uint_as_float(p2) + __uint_as_float(p3);
            // C-frag (c0,c1,c2,c3) -> A-frag = (c0, c2, c1, c3)
            pa[mnt][0] = p0; pa[mnt][1] = p2; pa[mnt][2] = p1; pa[mnt][3] = p3;
        }

        // prefetch next adj chunk under the AV MMAs
        if (c < 15) adjload(c + 1, ajn0, ajn1);

        // ---- O += P @ X^T ----
#pragma unroll
        for (int nt = 0; nt < 19; nt++) {
            const char* xrow = xb + (dh * 152 + nt * 8 + g) * XSTRIDE;
#pragma unroll
            for (int kt = 0; kt < 4; kt++) {
                ull xv = *(const ull*)(xrow + kt * 32 + 8 * t);
                mma8(oacc[nt], pa[kt], (u32)xv, (u32)(xv >> 32));
            }
        }

#pragma unroll
        for (int mnt = 0; mnt < 4; mnt++) { ajc0[mnt] = ajn0[mnt]; ajc1[mnt] = ajn1[mnt]; }
        __syncthreads();   // all reads of buf (c&1) done before it is restaged
    }

    // ---- rowsum reduce across the t-quad ----
    {
        float v = r0s;
        v += __shfl_xor_sync(0xffffffffu, v, 1);
        v += __shfl_xor_sync(0xffffffffu, v, 2);
        r0s = v;
        v = r1s;
        v += __shfl_xor_sync(0xffffffffu, v, 1);
        v += __shfl_xor_sync(0xffffffffu, v, 2);
        r1s = v;
    }

    // ---- normalize + store ----
    {
        const float i0 = 1.0f / r0s;
        const float i1 = 1.0f / r1s;
        float* r0p = out + (long)(qbase + g) * DD;
        float* r1p = out + (long)(qbase + 8 + g) * DD;
#pragma unroll
        for (int nt = 0; nt < 19; nt++) {
            const int d = dh * 152 + nt * 8 + 2 * t;
            if (d < 299) {
                *(float2*)(r0p + d) = make_float2(oacc[nt].x * i0, oacc[nt].y * i0);
                *(float2*)(r1p + d) = make_float2(oacc[nt].z * i1, oacc[nt].w * i1);
            }
        }
    }
}

// ---------------------------------------------------------------------------
extern "C" void kernel_launch(void* const* d_in, const int* in_sizes, int n_in,
                              void* d_out, int out_size)
{
    const float* X   = (const float*)d_in[0];
    const float* adj = (const float*)d_in[1];
    const float* Wq  = (const float*)d_in[2];
    const float* Wk  = (const float*)d_in[3];
    float* out = (float*)d_out;

    cudaFuncSetAttribute(attn_mma_kernel,
                         cudaFuncAttributeMaxDynamicSharedMemorySize, SM_TOT);

    qk_kernel<<<(BB * NN) / 128, 256>>>(X, Wq, Wk);
    attn_mma_kernel<<<BB * 8, 256, SM_TOT>>>(adj, out);
}

// round 15
// speedup vs baseline: 1.7819x; 1.0294x over previous
#include <cuda_runtime.h>

#define BB 128
#define NN 512
#define DD 300
#define AA 32

typedef unsigned long long ull;
typedef unsigned int u32;

// ---------------- helpers ----------------
__device__ __forceinline__ void fma2(ull& d, ull a, ull b) {
    asm("fma.rn.f32x2 %0, %1, %2, %0;" : "+l"(d) : "l"(a), "l"(b));
}
__device__ __forceinline__ ull dup2(float x) {
    ull r; asm("mov.b64 %0, {%1, %1};" : "=l"(r) : "f"(x)); return r;
}
__device__ __forceinline__ void unpack2(ull v, float& lo, float& hi) {
    asm("mov.b64 {%0, %1}, %2;" : "=f"(lo), "=f"(hi) : "l"(v));
}
__device__ __forceinline__ u32 tf32r(float x) {
    u32 r; asm("cvt.rna.tf32.f32 %0, %1;" : "=r"(r) : "f"(x)); return r;
}
__device__ __forceinline__ void mma8(float4& d, const u32* a, u32 b0, u32 b1) {
    asm volatile(
        "mma.sync.aligned.m16n8k8.row.col.f32.tf32.tf32.f32 "
        "{%0,%1,%2,%3}, {%4,%5,%6,%7}, {%8,%9}, {%0,%1,%2,%3};"
        : "+f"(d.x), "+f"(d.y), "+f"(d.z), "+f"(d.w)
        : "r"(a[0]), "r"(a[1]), "r"(a[2]), "r"(a[3]), "r"(b0), "r"(b1));
}
__device__ __forceinline__ u32 smem_u32(const void* p) {
    u32 a; asm("{ .reg .u64 t; cvta.to.shared.u64 t, %1; cvt.u32.u64 %0, t; }"
               : "=r"(a) : "l"(p));
    return a;
}
__device__ __forceinline__ void cp16(u32 dst, const void* src) {
    asm volatile("cp.async.cg.shared.global [%0], [%1], 16;"
                 :: "r"(dst), "l"(src) : "memory");
}
#define CP_COMMIT() asm volatile("cp.async.commit_group;" ::: "memory")
#define CP_WAIT2()  asm volatile("cp.async.wait_group 2;" ::: "memory")
#define CP_WAIT1()  asm volatile("cp.async.wait_group 1;" ::: "memory")
#define CP_WAIT0()  asm volatile("cp.async.wait_group 0;" ::: "memory")

// Scratch: Q,K row-major [B*N, A] (tf32-rounded); Xt = X^T per batch [B][304][512]
__device__ float g_Q[BB * NN * AA];
__device__ float g_K[BB * NN * AA];
__device__ float g_Xt[(long)BB * 304 * 512];   // d rows 300..303 stay zero

// ---------------------------------------------------------------------------
// Kernel 1: Q|K projection (FFMA2) + X transpose writeout, tf32-rounded outs.
// Round-8 version: 256 rows x 64 cols per block, register double-buffer.
// ---------------------------------------------------------------------------
__global__ __launch_bounds__(256) void qk_kernel(
    const float* __restrict__ X,
    const float* __restrict__ Wq,
    const float* __restrict__ Wk)
{
    __shared__ float Xs[256 * 9];
    __shared__ float Ws[8 * 68];

    const int tid = threadIdx.x;
    const int row0 = blockIdx.x * 256;
    const int rg = tid >> 3;
    const int cg = tid & 7;

    ull acc[8][4];
#pragma unroll
    for (int i = 0; i < 8; i++)
#pragma unroll
        for (int j = 0; j < 4; j++) acc[i][j] = 0ull;

    float xf[8], wf[2];
    const float* xrow = X + (long)(row0 + tid) * DD;
    const int wk0 = tid >> 6, wa0 = tid & 63;
    const int wk1 = (tid + 256) >> 6, wa1 = (tid + 256) & 63;

    auto prefetch = [&](int k0) {
        if (k0 + 8 <= DD) {
            float4 v0 = *(const float4*)(xrow + k0);
            float4 v1 = *(const float4*)(xrow + k0 + 4);
            xf[0] = v0.x; xf[1] = v0.y; xf[2] = v0.z; xf[3] = v0.w;
            xf[4] = v1.x; xf[5] = v1.y; xf[6] = v1.z; xf[7] = v1.w;
        } else {
#pragma unroll
            for (int kk = 0; kk < 8; kk++)
                xf[kk] = (k0 + kk < DD) ? xrow[k0 + kk] : 0.0f;
        }
        wf[0] = (k0 + wk0 < DD)
              ? ((wa0 < 32) ? Wq[(k0 + wk0) * AA + wa0] : Wk[(k0 + wk0) * AA + wa0 - 32]) : 0.0f;
        wf[1] = (k0 + wk1 < DD)
              ? ((wa1 < 32) ? Wq[(k0 + wk1) * AA + wa1] : Wk[(k0 + wk1) * AA + wa1 - 32]) : 0.0f;
    };

    prefetch(0);

    for (int k0 = 0; k0 < DD; k0 += 8) {
        {
            float* xs = &Xs[tid * 9];
#pragma unroll
            for (int kk = 0; kk < 8; kk++) xs[kk] = xf[kk];
            Ws[wk0 * 68 + wa0] = wf[0];
            Ws[wk1 * 68 + wa1] = wf[1];
        }
        __syncthreads();
        if (k0 + 8 < DD) prefetch(k0 + 8);

        // transpose writeout: Xs[256 rows][8 d] -> g_Xt[b][d][m], tf32-rounded
        {
            const int dloc = tid >> 5, lane = tid & 31;
            const int d = k0 + dloc;
            if (d < DD) {
                const int bb = row0 >> 9;
                const int m0g = row0 & 511;
                float* dst = g_Xt + ((long)bb * 304 + d) * 512 + m0g + lane;
#pragma unroll
                for (int i = 0; i < 8; i++)
                    dst[32 * i] = __uint_as_float(tf32r(Xs[(lane + 32 * i) * 9 + dloc]));
            }
        }

#pragma unroll
        for (int k = 0; k < 8; k++) {
            ull ad[8];
#pragma unroll
            for (int i = 0; i < 8; i++) ad[i] = dup2(Xs[(rg * 8 + i) * 9 + k]);
            ull bv[4];
#pragma unroll
            for (int j = 0; j < 4; j++)
                bv[j] = *(const ull*)&Ws[k * 68 + cg * 8 + 2 * j];
#pragma unroll
            for (int i = 0; i < 8; i++)
#pragma unroll
                for (int j = 0; j < 4; j++) fma2(acc[i][j], bv[j], ad[i]);
        }
        __syncthreads();
    }

#pragma unroll
    for (int i = 0; i < 8; i++) {
        const int row = row0 + rg * 8 + i;
#pragma unroll
        for (int j = 0; j < 4; j++) {
            const int c = cg * 8 + 2 * j;
            float lo, hi; unpack2(acc[i][j], lo, hi);
            ull packed = (ull)tf32r(lo) | ((ull)tf32r(hi) << 32);
            if (c < 32) *(ull*)&g_Q[row * AA + c] = packed;
            else        *(ull*)&g_K[row * AA + (c - 32)] = packed;
        }
    }
}

// ---------------------------------------------------------------------------
// Kernel 2: warp-MMA (tf32) fused attention, cp.async TRIPLE-buffered
// (stage ahead by 2 chunks; wait_group 2 steady-state).
// Per-warp structure identical to the validated round-8 kernel (regs ~217).
// smem per buffer: Xs [304 d][stride 160B] = 48640 ; Ks [32 m][128B swz] = 4096
// ---------------------------------------------------------------------------
#define XSTRIDE 160
#define KOFF    48640
#define BUFSZ   52736
#define SM_TOT  (3 * BUFSZ)

__global__ __launch_bounds__(256, 1) void attn_mma_kernel(
    const float* __restrict__ adj,
    float* __restrict__ out)
{
    extern __shared__ char smc[];
    const u32 sb = smem_u32(smc);
    const int tid = threadIdx.x;
    const int lane = tid & 31, w = tid >> 5;
    const int g = lane >> 2, t = lane & 3;
    const int qg = w & 3, dh = w >> 2;
    const int b = blockIdx.x >> 3, row0 = (blockIdx.x & 7) * 64;
    const int qbase = b * NN + row0 + qg * 16;   // 16 q rows per group

    // ---- staging lambda (cp.async, one commit per call) ----
    auto stage = [&](int cc, int bi) {
        const int m0 = cc * 32;
        const u32 bx = sb + bi * BUFSZ;
        {   // Ks: 32 rows x 2 x 16B ; 256 cps
            int row = tid >> 3, m4 = tid & 7;
            u32 dst = bx + KOFF + row * 128 + ((m4 * 16) ^ ((row & 7) << 4));
            cp16(dst, g_K + ((long)(b * NN + m0 + row)) * AA + m4 * 4);
        }
#pragma unroll
        for (int tt = 0; tt < 10; tt++) {   // Xs: 304 rows x 8 x 16B = 2432 cps
            int idx = tid + tt * 256;
            if (idx < 2432) {
                int d = idx >> 3, m4 = idx & 7;
                u32 dst = bx + d * XSTRIDE + m4 * 16;
                cp16(dst, g_Xt + ((long)b * 304 + d) * 512 + m0 + m4 * 4);
            }
        }
    };

    // ---- adj fragment prefetch (direct LDG.64, natural layout) ----
    ull ajc0[4], ajc1[4], ajn0[4], ajn1[4];
    const float* ar0 = adj + (long)(qbase + g) * NN + 2 * t;
    const float* ar1 = adj + (long)(qbase + 8 + g) * NN + 2 * t;
    auto adjload = [&](int cc, ull* a0, ull* a1) {
        const int m0 = cc * 32;
#pragma unroll
        for (int mnt = 0; mnt < 4; mnt++) {
            a0[mnt] = *(const ull*)(ar0 + m0 + mnt * 8);
            a1[mnt] = *(const ull*)(ar1 + m0 + mnt * 8);
        }
    };

    // ---- Q fragments: persistent in registers ----
    u32 qa[4][4];
    {
        const float* q0 = g_Q + (long)(qbase + g) * AA;
        const float* q1 = g_Q + (long)(qbase + 8 + g) * AA;
#pragma unroll
        for (int kt = 0; kt < 4; kt++) {
            qa[kt][0] = __float_as_uint(q0[8 * kt + t]);
            qa[kt][1] = __float_as_uint(q1[8 * kt + t]);
            qa[kt][2] = __float_as_uint(q0[8 * kt + t + 4]);
            qa[kt][3] = __float_as_uint(q1[8 * kt + t + 4]);
        }
    }

    stage(0, 0);
    CP_COMMIT();
    stage(1, 1);
    CP_COMMIT();
    adjload(0, ajc0, ajc1);

    float4 oacc[19];
#pragma unroll
    for (int nt = 0; nt < 19; nt++) oacc[nt] = make_float4(0.f, 0.f, 0.f, 0.f);
    float r0s = 0.f, r1s = 0.f;

#pragma unroll 1
    for (int c = 0; c < 16; c++) {
        // stage chunk c+2 into buffer (c+2)%3 — that buffer was used by chunk
        // c-1, whose compute finished before this iteration's start (end-of-
        // iteration __syncthreads).
        if (c < 14) {
            stage(c + 2, (c + 2) % 3);
            CP_COMMIT();
            CP_WAIT2();
        } else if (c == 14) {
            CP_WAIT1();
        } else {
            CP_WAIT0();
        }
        __syncthreads();

        const char* xb = smc + (c % 3) * BUFSZ;
        const char* kb = xb + KOFF;

        // ---- S = Q K^T per mnt, fused exp(s*adj), build A-frags of P ----
        u32 pa[4][4];
#pragma unroll
        for (int mnt = 0; mnt < 4; mnt++) {
            const char* krow = kb + (8 * mnt + g) * 128;
            float4 s = make_float4(0.f, 0.f, 0.f, 0.f);
#pragma unroll
            for (int kt = 0; kt < 4; kt++) {
                u32 b0 = *(const u32*)(krow + (((8 * kt + t) * 4) ^ (g << 4)));
                u32 b1 = *(const u32*)(krow + (((8 * kt + t + 4) * 4) ^ (g << 4)));
                mma8(s, qa[kt], b0, b1);
            }
            float ax, ay, az, aw;
            unpack2(ajc0[mnt], ax, ay);
            unpack2(ajc1[mnt], az, aw);
            u32 p0 = tf32r(__expf(s.x * ax));
            u32 p1 = tf32r(__expf(s.y * ay));
            u32 p2 = tf32r(__expf(s.z * az));
            u32 p3 = tf32r(__expf(s.w * aw));
            r0s += __uint_as_float(p0) + __uint_as_float(p1);
            r1s += __uint_as_float(p2) + __uint_as_float(p3);
            // C-frag (c0,c1,c2,c3) -> A-frag = (c0, c2, c1, c3)
            pa[mnt][0] = p0; pa[mnt][1] = p2; pa[mnt][2] = p1; pa[mnt][3] = p3;
        }

        // prefetch next adj chunk under the AV MMAs
        if (c < 15) adjload(c + 1, ajn0, ajn1);

        // ---- O += P @ X^T ----
#pragma unroll
        for (int nt = 0; nt < 19; nt++) {
            const char* xrow = xb + (dh * 152 + nt * 8 + g) * XSTRIDE;
#pragma unroll
            for (int kt = 0; kt < 4; kt++) {
                ull xv = *(const ull*)(xrow + kt * 32 + 8 * t);
                mma8(oacc[nt], pa[kt], (u32)xv, (u32)(xv >> 32));
            }
        }

#pragma unroll
        for (int mnt = 0; mnt < 4; mnt++) { ajc0[mnt] = ajn0[mnt]; ajc1[mnt] = ajn1[mnt]; }
        __syncthreads();   // all reads of buf (c%3) done before it is restaged
    }

    // ---- rowsum reduce across the t-quad ----
    {
        float v = r0s;
        v += __shfl_xor_sync(0xffffffffu, v, 1);
        v += __shfl_xor_sync(0xffffffffu, v, 2);
        r0s = v;
        v = r1s;
        v += __shfl_xor_sync(0xffffffffu, v, 1);
        v += __shfl_xor_sync(0xffffffffu, v, 2);
        r1s = v;
    }

    // ---- normalize + store ----
    {
        const float i0 = 1.0f / r0s;
        const float i1 = 1.0f / r1s;
        float* r0p = out + (long)(qbase + g) * DD;
        float* r1p = out + (long)(qbase + 8 + g) * DD;
#pragma unroll
        for (int nt = 0; nt < 19; nt++) {
            const int d = dh * 152 + nt * 8 + 2 * t;
            if (d < 299) {
                *(float2*)(r0p + d) = make_float2(oacc[nt].x * i0, oacc[nt].y * i0);
                *(float2*)(r1p + d) = make_float2(oacc[nt].z * i1, oacc[nt].w * i1);
            }
        }
    }
}

// ---------------------------------------------------------------------------
extern "C" void kernel_launch(void* const* d_in, const int* in_sizes, int n_in,
                              void* d_out, int out_size)
{
    const float* X   = (const float*)d_in[0];
    const float* adj = (const float*)d_in[1];
    const float* Wq  = (const float*)d_in[2];
    const float* Wk  = (const float*)d_in[3];
    float* out = (float*)d_out;

    cudaFuncSetAttribute(attn_mma_kernel,
                         cudaFuncAttributeMaxDynamicSharedMemorySize, SM_TOT);

    qk_kernel<<<(BB * NN) / 256, 256>>>(X, Wq, Wk);
    attn_mma_kernel<<<BB * 8, 256, SM_TOT>>>(adj, out);
}